// round 14
// baseline (speedup 1.0000x reference)
#include <cuda_runtime.h>
#include <math.h>

#define NTOK 4096
#define DIM  1024
#define NEXP 8
#define CAP  1280
#define NSLOT (NTOK * 2)
#define ROWW (NEXP * CAP)            // 10240 floats per mask token-row

// ---- node 1: logits (0..511) + zero-fill (512..2559). Lean, no sync.
#define B_LOG  512                   // 1 token/warp, 8 warps/block
#define B_ZERO 2048                  // 80 KB contiguous zero-fill each
#define NBLK1  (B_LOG + B_ZERO)      // 2560

// ---- node 3: batch rows only
#define B_BAT  (NEXP * CAP / 2)      // 2560 blocks? no: 5120 rows /2 = 5120... see below

// Scratch (no device allocs)
__device__ int g_topidx[NSLOT];      // expert id per slot
__device__ int g_pos[NSLOT];         // packed e*CAP+p, or -1 if dropped
__device__ int g_inv[NEXP * CAP];    // (e,pos) -> token, -1 if empty

// ---------------------------------------------------------------------------
// Node 1: logits (global-W via L1, no smem, no fences/atomics) + zero-fill.
// Exactly the R10 shape that ran at ~6.8 TB/s store throughput.
// ---------------------------------------------------------------------------
__global__ __launch_bounds__(256) void k_pre(const float* __restrict__ x,
                                             const float* __restrict__ Wg,
                                             float* __restrict__ gates,
                                             float* __restrict__ mask) {
    const int b = blockIdx.x;

    if (b >= B_LOG) {
        // ----- mask zero-fill: stores only -----
        int zb = b - B_LOG;                          // 0 .. 2047
        float4* dst = (float4*)mask + (size_t)zb * (256 * 20) + threadIdx.x;
        const float4 z = make_float4(0.f, 0.f, 0.f, 0.f);
#pragma unroll
        for (int j = 0; j < 20; j++)
            __stcs(dst + j * 256, z);
        return;
    }

    // ----- logits: 1 token/warp, x + W from global (W broadcast -> L1) -----
    int warp = threadIdx.x >> 5;
    int lane = threadIdx.x & 31;
    int t = b * 8 + warp;

    const float4* xr = (const float4*)x + (size_t)t * (DIM / 4);
    const float4* W4 = (const float4*)Wg;

    float acc[NEXP];
#pragma unroll
    for (int e = 0; e < NEXP; e++) acc[e] = 0.f;

#pragma unroll
    for (int i = 0; i < 8; i++) {
        int o = lane + 32 * i;
        float4 v = xr[o];
#pragma unroll
        for (int e = 0; e < NEXP; e++) {
            float4 w = W4[e * 256 + o];
            acc[e] += v.x * w.x + v.y * w.y + v.z * w.z + v.w * w.w;
        }
    }
#pragma unroll
    for (int off = 16; off; off >>= 1)
#pragma unroll
        for (int e = 0; e < NEXP; e++)
            acc[e] += __shfl_xor_sync(0xffffffffu, acc[e], off);

    if (lane == 0) {
        float v1 = -1e30f, v2 = -1e30f;
        int i1 = 0, i2 = 0;
#pragma unroll
        for (int e = 0; e < NEXP; e++) {
            float a = acc[e];
            if (a > v1)      { v2 = v1; i2 = i1; v1 = a; i1 = e; }
            else if (a > v2) { v2 = a;  i2 = e; }
        }
        float e2 = expf(v2 - v1);
        float inv = 1.f / (1.f + e2);
        gates[2 * t]     = inv;
        gates[2 * t + 1] = e2 * inv;
        g_topidx[2 * t]     = i1;
        g_topidx[2 * t + 1] = i2;
    }
}

// ---------------------------------------------------------------------------
// Node 2 (1 block): scan -> positions + inverse map, then scatter the <=8192
// gate values into the (already zeroed) mask. Node edges provide ordering.
// ---------------------------------------------------------------------------
__global__ __launch_bounds__(256) void k_mid(const float* __restrict__ gates,
                                             float* __restrict__ mask) {
    __shared__ uint4 ssc[256];
    int tid = threadIdx.x;

    for (int i = tid; i < NEXP * CAP; i += 256) g_inv[i] = -1;

    int base = tid * 32;
    unsigned short h[NEXP];
#pragma unroll
    for (int e = 0; e < NEXP; e++) h[e] = 0;
#pragma unroll
    for (int j = 0; j < 32; j++) h[g_topidx[base + j]]++;

    uint4 v;
    v.x = (unsigned)h[0] | ((unsigned)h[1] << 16);
    v.y = (unsigned)h[2] | ((unsigned)h[3] << 16);
    v.z = (unsigned)h[4] | ((unsigned)h[5] << 16);
    v.w = (unsigned)h[6] | ((unsigned)h[7] << 16);
    ssc[tid] = v;
    __syncthreads();
    for (int off = 1; off < 256; off <<= 1) {
        uint4 a = make_uint4(0, 0, 0, 0);
        if (tid >= off) a = ssc[tid - off];
        __syncthreads();
        v.x += a.x; v.y += a.y; v.z += a.z; v.w += a.w;
        ssc[tid] = v;
        __syncthreads();
    }

    int cnt[NEXP];
    cnt[0] = (int)(v.x & 0xFFFF) - (int)h[0];
    cnt[1] = (int)(v.x >> 16)    - (int)h[1];
    cnt[2] = (int)(v.y & 0xFFFF) - (int)h[2];
    cnt[3] = (int)(v.y >> 16)    - (int)h[3];
    cnt[4] = (int)(v.z & 0xFFFF) - (int)h[4];
    cnt[5] = (int)(v.z >> 16)    - (int)h[5];
    cnt[6] = (int)(v.w & 0xFFFF) - (int)h[6];
    cnt[7] = (int)(v.w >> 16)    - (int)h[7];

#pragma unroll
    for (int j = 0; j < 32; j++) {
        int slot = base + j;
        int e = g_topidx[slot];                      // L1-hot reread
        int p = cnt[e]++;
        if (p < CAP) {
            int off = e * CAP + p;
            g_pos[slot] = off;
            g_inv[off] = slot >> 1;
            // scatter gate into zeroed mask right here
            mask[(size_t)(slot >> 1) * ROWW + off] = gates[slot];
        } else {
            g_pos[slot] = -1;
        }
    }
}

// ---------------------------------------------------------------------------
// Node 3: exp_batches only — lean store kernel, 2 rows per block.
// ---------------------------------------------------------------------------
#define NB_BAT (NEXP * CAP / 2)      // 5120 blocks

__global__ __launch_bounds__(256) void k_bat(const float* __restrict__ x,
                                             float* __restrict__ batch) {
    int r0 = blockIdx.x * 2;
#pragma unroll
    for (int j = 0; j < 2; j++) {
        int r = r0 + j;
        int t = g_inv[r];
        float4 v = make_float4(0.f, 0.f, 0.f, 0.f);
        if (t >= 0)
            v = ((const float4*)x)[(size_t)t * (DIM / 4) + threadIdx.x];
        __stcs((float4*)batch + (size_t)r * (DIM / 4) + threadIdx.x, v);
    }
}

// ---------------------------------------------------------------------------
extern "C" void kernel_launch(void* const* d_in, const int* in_sizes, int n_in,
                              void* d_out, int out_size) {
    const float* x  = (const float*)d_in[0];   // [2,2048,1024] f32
    const float* Wg = (const float*)d_in[1];   // [8,1024] f32

    float* out   = (float*)d_out;
    float* gates = out;                                  // 8,192 floats
    float* mask  = out + (size_t)NSLOT;                  // 41,943,040 floats
    float* batch = mask + (size_t)NTOK * ROWW;           // 10,485,760 floats

    k_pre<<<NBLK1, 256>>>(x, Wg, gates, mask);
    k_mid<<<1, 256>>>(gates, mask);
    k_bat<<<NB_BAT, 256>>>(x, batch);
}

// round 15
// speedup vs baseline: 1.2732x; 1.2732x over previous
#include <cuda_runtime.h>
#include <math.h>

#define NTOK 4096
#define DIM  1024
#define NEXP 8
#define CAP  1280
#define NSLOT (NTOK * 2)
#define ROWW (NEXP * CAP)            // 10240 floats per mask token-row

// ---- node 1: logits (0..511) + zero-fill (512..2559). Lean, proven 30.3us.
#define B_LOG  512
#define B_ZERO 2048
#define NBLK1  (B_LOG + B_ZERO)

// ---- node 2: scan (bid 0) + batch (1..5120) + scatter (5121..5152)
#define B_BAT  (NEXP * CAP / 2)      // 5120 blocks, 2 rows each
#define SCAT0  (1 + B_BAT)           // 5121
#define NBLK2  (SCAT0 + NSLOT / 256) // 5153

// Scratch (no device allocs). Sentinel protocol (0 = not ready, zero-init ok):
//   g_inv: 0 not-ready | t+1 token | -1 empty.  Reset to 0 by batch consumer.
//   g_pos: 0 not-ready | off+1     | -1 dropped. Reset to 0 by scatter consumer.
__device__ int g_topidx[NSLOT];
__device__ int g_pos[NSLOT];
__device__ int g_inv[NEXP * CAP];

// ---------------------------------------------------------------------------
// Node 1: logits (global-W via L1, no smem/fences/atomics) + mask zero-fill.
// ---------------------------------------------------------------------------
__global__ __launch_bounds__(256) void k_pre(const float* __restrict__ x,
                                             const float* __restrict__ Wg,
                                             float* __restrict__ gates,
                                             float* __restrict__ mask) {
    const int b = blockIdx.x;

    if (b >= B_LOG) {
        int zb = b - B_LOG;
        float4* dst = (float4*)mask + (size_t)zb * (256 * 20) + threadIdx.x;
        const float4 z = make_float4(0.f, 0.f, 0.f, 0.f);
#pragma unroll
        for (int j = 0; j < 20; j++)
            __stcs(dst + j * 256, z);
        return;
    }

    int warp = threadIdx.x >> 5;
    int lane = threadIdx.x & 31;
    int t = b * 8 + warp;

    const float4* xr = (const float4*)x + (size_t)t * (DIM / 4);
    const float4* W4 = (const float4*)Wg;

    float acc[NEXP];
#pragma unroll
    for (int e = 0; e < NEXP; e++) acc[e] = 0.f;

#pragma unroll
    for (int i = 0; i < 8; i++) {
        int o = lane + 32 * i;
        float4 v = xr[o];
#pragma unroll
        for (int e = 0; e < NEXP; e++) {
            float4 w = W4[e * 256 + o];
            acc[e] += v.x * w.x + v.y * w.y + v.z * w.z + v.w * w.w;
        }
    }
#pragma unroll
    for (int off = 16; off; off >>= 1)
#pragma unroll
        for (int e = 0; e < NEXP; e++)
            acc[e] += __shfl_xor_sync(0xffffffffu, acc[e], off);

    if (lane == 0) {
        float v1 = -1e30f, v2 = -1e30f;
        int i1 = 0, i2 = 0;
#pragma unroll
        for (int e = 0; e < NEXP; e++) {
            float a = acc[e];
            if (a > v1)      { v2 = v1; i2 = i1; v1 = a; i1 = e; }
            else if (a > v2) { v2 = a;  i2 = e; }
        }
        float e2 = expf(v2 - v1);
        float inv = 1.f / (1.f + e2);
        gates[2 * t]     = inv;
        gates[2 * t + 1] = e2 * inv;
        g_topidx[2 * t]     = i1;
        g_topidx[2 * t + 1] = i2;
    }
}

// ---------------------------------------------------------------------------
// Node 2: bid 0 = scan (no waiting; node edge ordered g_topidx).
//         bids 1..5120 = batch rows, poll OWN g_inv entries (distinct addrs).
//         bids 5121..  = gate scatter, poll OWN g_pos entry (distinct addrs).
// Every sentinel written once with final value; consumer resets to 0.
// ---------------------------------------------------------------------------
__global__ __launch_bounds__(256) void k_post(const float* __restrict__ x,
                                              const float* __restrict__ gates,
                                              float* __restrict__ mask,
                                              float* __restrict__ batch) {
    __shared__ uint4 ssc[256];                       // scan branch only (4 KB)
    const int b = blockIdx.x;

    if (b == 0) {
        // ----- scan: histogram + packed prefix scan + single-shot emits -----
        int tid = threadIdx.x;
        int base = tid * 32;
        unsigned short h[NEXP];
#pragma unroll
        for (int e = 0; e < NEXP; e++) h[e] = 0;
#pragma unroll
        for (int j = 0; j < 32; j++) h[g_topidx[base + j]]++;

        uint4 v;
        v.x = (unsigned)h[0] | ((unsigned)h[1] << 16);
        v.y = (unsigned)h[2] | ((unsigned)h[3] << 16);
        v.z = (unsigned)h[4] | ((unsigned)h[5] << 16);
        v.w = (unsigned)h[6] | ((unsigned)h[7] << 16);
        ssc[tid] = v;
        __syncthreads();
        for (int off = 1; off < 256; off <<= 1) {
            uint4 a = make_uint4(0, 0, 0, 0);
            if (tid >= off) a = ssc[tid - off];
            __syncthreads();
            v.x += a.x; v.y += a.y; v.z += a.z; v.w += a.w;
            ssc[tid] = v;
            __syncthreads();
        }

        // per-expert totals (inclusive prefix of last thread)
        uint4 tot4 = ssc[255];
        int total[NEXP];
        total[0] = tot4.x & 0xFFFF;  total[1] = tot4.x >> 16;
        total[2] = tot4.y & 0xFFFF;  total[3] = tot4.y >> 16;
        total[4] = tot4.z & 0xFFFF;  total[5] = tot4.z >> 16;
        total[6] = tot4.w & 0xFFFF;  total[7] = tot4.w >> 16;

        int cnt[NEXP];
        cnt[0] = (int)(v.x & 0xFFFF) - (int)h[0];
        cnt[1] = (int)(v.x >> 16)    - (int)h[1];
        cnt[2] = (int)(v.y & 0xFFFF) - (int)h[2];
        cnt[3] = (int)(v.y >> 16)    - (int)h[3];
        cnt[4] = (int)(v.z & 0xFFFF) - (int)h[4];
        cnt[5] = (int)(v.z >> 16)    - (int)h[5];
        cnt[6] = (int)(v.w & 0xFFFF) - (int)h[6];
        cnt[7] = (int)(v.w >> 16)    - (int)h[7];

        // occupied entries: single-shot final values
#pragma unroll
        for (int j = 0; j < 32; j++) {
            int slot = base + j;
            int e = g_topidx[slot];
            int p = cnt[e]++;
            if (p < CAP) {
                g_pos[slot] = e * CAP + p + 1;           // off+1
                g_inv[e * CAP + p] = (slot >> 1) + 1;    // token+1
            } else {
                g_pos[slot] = -1;
            }
        }

        // empty entries (p >= total[e]): single-shot -1, disjoint from above
#pragma unroll
        for (int e = 0; e < NEXP; e++)
            for (int p = tid; p < CAP; p += 256)
                if (p >= total[e]) g_inv[e * CAP + p] = -1;
        return;
    }

    if (b < SCAT0) {
        // ----- batch: poll own 2 g_inv entries, copy/zero rows, reset -----
        __shared__ int st[2];
        int r0 = (b - 1) * 2;
        if (threadIdx.x < 2) {
            volatile int* vi = g_inv;
            int vv;
            while ((vv = vi[r0 + threadIdx.x]) == 0) __nanosleep(100);
            st[threadIdx.x] = vv;
            g_inv[r0 + threadIdx.x] = 0;                 // consume-reset
        }
        __syncthreads();
#pragma unroll
        for (int j = 0; j < 2; j++) {
            int vv = st[j];
            float4 val = make_float4(0.f, 0.f, 0.f, 0.f);
            if (vv > 0)
                val = ((const float4*)x)[(size_t)(vv - 1) * (DIM / 4) + threadIdx.x];
            __stcs((float4*)batch + (size_t)(r0 + j) * (DIM / 4) + threadIdx.x, val);
        }
        return;
    }

    // ----- scatter: poll own g_pos entry, write gate, reset -----
    int slot = (b - SCAT0) * 256 + threadIdx.x;          // 0 .. NSLOT-1
    volatile int* vp = g_pos;
    int vv;
    while ((vv = vp[slot]) == 0) __nanosleep(100);
    g_pos[slot] = 0;                                     // consume-reset
    if (vv > 0) {
        int tok = slot >> 1;
        mask[(size_t)tok * ROWW + (vv - 1)] = gates[slot];
    }
}

// ---------------------------------------------------------------------------
extern "C" void kernel_launch(void* const* d_in, const int* in_sizes, int n_in,
                              void* d_out, int out_size) {
    const float* x  = (const float*)d_in[0];   // [2,2048,1024] f32
    const float* Wg = (const float*)d_in[1];   // [8,1024] f32

    float* out   = (float*)d_out;
    float* gates = out;                                  // 8,192 floats
    float* mask  = out + (size_t)NSLOT;                  // 41,943,040 floats
    float* batch = mask + (size_t)NTOK * ROWW;           // 10,485,760 floats

    k_pre<<<NBLK1, 256>>>(x, Wg, gates, mask);
    k_post<<<NBLK2, 256>>>(x, gates, mask, batch);
}